// round 1
// baseline (speedup 1.0000x reference)
#include <cuda_runtime.h>

// PermuteWeightSharing: out[..., i*16+k] = x[..., p_pos[i]*16+k] - x[..., p_neg[i]*16+k]
// x: (512,16,16,256) fp32. Ppos/Pneg: 16x16 one-hot permutation matrices.
// Pure HBM-bound streaming permute: 128 MiB in + 128 MiB out.

#define NUM_SLOTS 16
#define ROW_F4 64              // 256 floats per row = 64 float4
#define SLOT_F4 4              // 16 floats per slot = 4 float4

__global__ __launch_bounds__(256, 8)
void permute_ws_kernel(const float4* __restrict__ x,
                       const float* __restrict__ Ppos,
                       const float* __restrict__ Pneg,
                       float4* __restrict__ out,
                       long long n_f4)
{
    // Decode permutation matrices once per block (tiny, L2-resident).
    __shared__ int s_pos[NUM_SLOTS];
    __shared__ int s_neg[NUM_SLOTS];
    if (threadIdx.x < NUM_SLOTS) {
        int i = threadIdx.x;
        int jp = 0, jn = 0;
        #pragma unroll
        for (int j = 0; j < NUM_SLOTS; ++j) {
            if (Ppos[i * NUM_SLOTS + j] > 0.5f) jp = j;
            if (Pneg[i * NUM_SLOTS + j] > 0.5f) jn = j;
        }
        s_pos[i] = jp;
        s_neg[i] = jn;
    }
    __syncthreads();

    long long g = (long long)blockIdx.x * blockDim.x + threadIdx.x;
    if (g >= n_f4) return;

    int c4   = (int)(g & (ROW_F4 - 1));     // float4 index within row [0,64)
    long long rowb = g - c4;                // base float4 index of this row
    int slot = c4 >> 2;                     // output slot [0,16)
    int k4   = c4 & (SLOT_F4 - 1);          // float4 within slot [0,4)

    const float4 a = x[rowb + s_pos[slot] * SLOT_F4 + k4];
    const float4 b = x[rowb + s_neg[slot] * SLOT_F4 + k4];

    float4 r;
    r.x = a.x - b.x;
    r.y = a.y - b.y;
    r.z = a.z - b.z;
    r.w = a.w - b.w;
    out[g] = r;
}

extern "C" void kernel_launch(void* const* d_in, const int* in_sizes, int n_in,
                              void* d_out, int out_size)
{
    const float4* x    = (const float4*)d_in[0];
    const float*  Ppos = (const float*)d_in[1];
    const float*  Pneg = (const float*)d_in[2];
    float4*       out  = (float4*)d_out;

    long long n_f4 = (long long)out_size / 4;   // out_size = 33,554,432 floats
    int threads = 256;
    long long blocks = (n_f4 + threads - 1) / threads;

    permute_ws_kernel<<<(unsigned)blocks, threads>>>(x, Ppos, Pneg, out, n_f4);
}

// round 2
// speedup vs baseline: 1.2522x; 1.2522x over previous
#include <cuda_runtime.h>

// PermuteWeightSharing: out[..., i*16+k] = x[..., p_pos[i]*16+k] - x[..., p_neg[i]*16+k]
// x: (512,16,16,256) fp32 -> 131072 rows of 256 floats (64 float4).
//
// R2 strategy: one warp per row. Row loaded ONCE, contiguously, into 2 float4
// regs per lane (v0 = chunk[lane], v1 = chunk[lane+32]). The slot permutation
// (64-chunk permutation, 16B granularity) is done in-register with warp
// shuffles + select. Global loads and stores are perfectly coalesced -> l1tex
// wavefronts drop from ~36/KB to 16/KB; kernel should become DRAM-bound.

#define NUM_SLOTS 16

__device__ __forceinline__ float4 row_gather(const float4& v0, const float4& v1, int s)
{
    // Fetch 16B chunk index s (0..63) of the row distributed as
    // v0 = chunk[lane], v1 = chunk[lane+32].
    int sl = s & 31;
    float4 a, b;
    a.x = __shfl_sync(0xFFFFFFFFu, v0.x, sl);
    a.y = __shfl_sync(0xFFFFFFFFu, v0.y, sl);
    a.z = __shfl_sync(0xFFFFFFFFu, v0.z, sl);
    a.w = __shfl_sync(0xFFFFFFFFu, v0.w, sl);
    b.x = __shfl_sync(0xFFFFFFFFu, v1.x, sl);
    b.y = __shfl_sync(0xFFFFFFFFu, v1.y, sl);
    b.z = __shfl_sync(0xFFFFFFFFu, v1.z, sl);
    b.w = __shfl_sync(0xFFFFFFFFu, v1.w, sl);
    return (s < 32) ? a : b;
}

__global__ __launch_bounds__(256, 8)
void permute_ws_shfl_kernel(const float4* __restrict__ x,
                            const float* __restrict__ Ppos,
                            const float* __restrict__ Pneg,
                            float4* __restrict__ out,
                            int nrows)
{
    __shared__ int s_pos[NUM_SLOTS];
    __shared__ int s_neg[NUM_SLOTS];
    int t = threadIdx.x;
    if (t < NUM_SLOTS) {
        int jp = 0, jn = 0;
        #pragma unroll
        for (int j = 0; j < NUM_SLOTS; ++j) {
            if (Ppos[t * NUM_SLOTS + j] > 0.5f) jp = j;
            if (Pneg[t * NUM_SLOTS + j] > 0.5f) jn = j;
        }
        s_pos[t] = jp;
        s_neg[t] = jn;
    }
    __syncthreads();

    int lane = t & 31;
    int warp = t >> 5;
    int row  = blockIdx.x * (blockDim.x >> 5) + warp;
    if (row >= nrows) return;

    // Per-lane source chunk indices for the two output chunks this lane owns.
    int d0 = lane;          // output chunk 0..31
    int d1 = lane + 32;     // output chunk 32..63
    int sp0 = s_pos[d0 >> 2] * 4 + (d0 & 3);
    int sn0 = s_neg[d0 >> 2] * 4 + (d0 & 3);
    int sp1 = s_pos[d1 >> 2] * 4 + (d1 & 3);
    int sn1 = s_neg[d1 >> 2] * 4 + (d1 & 3);

    const float4* __restrict__ r = x + (long long)row * 64;
    float4*       __restrict__ o = out + (long long)row * 64;

    // Contiguous, read-once row load.
    float4 v0 = r[lane];
    float4 v1 = r[lane + 32];

    float4 a0 = row_gather(v0, v1, sp0);
    float4 b0 = row_gather(v0, v1, sn0);
    float4 a1 = row_gather(v0, v1, sp1);
    float4 b1 = row_gather(v0, v1, sn1);

    float4 o0, o1;
    o0.x = a0.x - b0.x;  o0.y = a0.y - b0.y;
    o0.z = a0.z - b0.z;  o0.w = a0.w - b0.w;
    o1.x = a1.x - b1.x;  o1.y = a1.y - b1.y;
    o1.z = a1.z - b1.z;  o1.w = a1.w - b1.w;

    // Contiguous stores.
    o[lane]      = o0;
    o[lane + 32] = o1;
}

extern "C" void kernel_launch(void* const* d_in, const int* in_sizes, int n_in,
                              void* d_out, int out_size)
{
    const float4* x    = (const float4*)d_in[0];
    const float*  Ppos = (const float*)d_in[1];
    const float*  Pneg = (const float*)d_in[2];
    float4*       out  = (float4*)d_out;

    int nrows = out_size / 256;                 // 131072 rows of 256 floats
    int threads = 256;                          // 8 warps -> 8 rows per block
    int rows_per_block = threads / 32;
    int blocks = (nrows + rows_per_block - 1) / rows_per_block;

    permute_ws_shfl_kernel<<<blocks, threads>>>(x, Ppos, Pneg, out, nrows);
}

// round 3
// speedup vs baseline: 1.2598x; 1.0061x over previous
#include <cuda_runtime.h>

// PermuteWeightSharing: out[..., i*16+k] = x[..., p[i]*16+k] - x[..., n[i]*16+k]
// x: (512,16,16,256) fp32 = 131072 rows x 256 floats (64 x 16B chunks, 16 slots of 64B).
//
// R3: one warp per row, row held as v0=chunk[lane], v1=chunk[lane+32].
// The 64-chunk permutation (2 chunks per lane) forms a 2-regular bipartite
// multigraph src-lane -> dst-lane; it decomposes into 2 perfect matchings.
// Pre-select (ALU) at the source puts the matching-0 chunk in r0, matching-1
// in r1; ONE shfl per register per operand then delivers everything:
// 16 shfl/row total (information floor) vs 32 before. Loads/stores stay
// fully coalesced. Routing tables built once by a tiny setup kernel.

#define FULLMASK 0xFFFFFFFFu

__device__ int d_route[32];   // packed per-lane routing (pos in low 16b, neg in high 16b)

// ---------------------------------------------------------------------------
// Setup: decode one-hot perms, 2-color the slot-level routing multigraph
// (edges = 16 out-slots; dst-partner(i) = i^8, src-partner(i) = Pinv[P[i]^8]),
// emit per-lane packed route words.
// ---------------------------------------------------------------------------
__global__ void route_setup(const float* __restrict__ Ppos,
                            const float* __restrict__ Pneg)
{
    __shared__ int P[2][16], Pinv[2][16], col[2][16];
    int t = threadIdx.x;              // 32 threads

    if (t < 32) {
        int o = t >> 4, i = t & 15;
        const float* M = o ? Pneg : Ppos;
        int js = 0;
        #pragma unroll
        for (int j = 0; j < 16; ++j)
            if (M[i * 16 + j] > 0.5f) js = j;
        P[o][i] = js;                 // out slot i sources from in slot js
    }
    __syncthreads();
    if (t < 32) { int o = t >> 4, i = t & 15; Pinv[o][P[o][i]] = i; }
    __syncthreads();

    if (t < 2) {                      // one thread per operand: cycle walk
        int o = t;
        for (int i = 0; i < 16; ++i) col[o][i] = -1;
        for (int st = 0; st < 16; ++st) {
            if (col[o][st] >= 0) continue;
            int e = st, c = 0;
            while (col[o][e] < 0) {
                col[o][e] = c;        // edge e gets color c
                int f = e ^ 8;        // dst partner: opposite color
                col[o][f] = 1 - c;
                e = Pinv[o][P[o][f] ^ 8];   // src partner of f: color c again
            }
        }
    }
    __syncthreads();

    if (t < 32) {
        int l = t, g = l >> 2, k = l & 3;
        unsigned rt = 0;
        #pragma unroll
        for (int o = 0; o < 2; ++o) {
            int ilo = g, ihi = g + 8;
            int c_lo = col[o][ilo];               // colors of lo/hi edges differ
            int i0 = (c_lo == 0) ? ilo : ihi;     // this dst lane's color-0 edge
            int i1 = (c_lo == 0) ? ihi : ilo;
            int src1 = 4 * (P[o][i0] & 7) + k;    // src lane for matching 0
            int src2 = 4 * (P[o][i1] & 7) + k;    // src lane for matching 1
            int swp  = c_lo;                      // 1: matching-0 delivers hi
            int sel  = col[o][Pinv[o][g]];        // 1: this lane's color-0 chunk is v1
            rt |= (unsigned)(src1 | (src2 << 5) | (sel << 10) | (swp << 11)) << (16 * o);
        }
        d_route[l] = (int)rt;
    }
}

// ---------------------------------------------------------------------------
// Main kernel
// ---------------------------------------------------------------------------
__device__ __forceinline__ void route_gather(
    const float4 v0, const float4 v1,
    int s1, int s2, unsigned sel, unsigned swp,
    float4& lo, float4& hi)
{
    float4 r0, r1;                                // source-side pre-select (ALU)
    r0.x = sel ? v1.x : v0.x;   r1.x = sel ? v0.x : v1.x;
    r0.y = sel ? v1.y : v0.y;   r1.y = sel ? v0.y : v1.y;
    r0.z = sel ? v1.z : v0.z;   r1.z = sel ? v0.z : v1.z;
    r0.w = sel ? v1.w : v0.w;   r1.w = sel ? v0.w : v1.w;

    float4 t1, t2;                                // one shfl per register
    t1.x = __shfl_sync(FULLMASK, r0.x, s1);
    t1.y = __shfl_sync(FULLMASK, r0.y, s1);
    t1.z = __shfl_sync(FULLMASK, r0.z, s1);
    t1.w = __shfl_sync(FULLMASK, r0.w, s1);
    t2.x = __shfl_sync(FULLMASK, r1.x, s2);
    t2.y = __shfl_sync(FULLMASK, r1.y, s2);
    t2.z = __shfl_sync(FULLMASK, r1.z, s2);
    t2.w = __shfl_sync(FULLMASK, r1.w, s2);

    lo.x = swp ? t2.x : t1.x;   hi.x = swp ? t1.x : t2.x;   // dst-side post-select
    lo.y = swp ? t2.y : t1.y;   hi.y = swp ? t1.y : t2.y;
    lo.z = swp ? t2.z : t1.z;   hi.z = swp ? t1.z : t2.z;
    lo.w = swp ? t2.w : t1.w;   hi.w = swp ? t1.w : t2.w;
}

__global__ __launch_bounds__(256)
void permute_ws_benes(const float4* __restrict__ x,
                      float4* __restrict__ out,
                      int nrows)
{
    int t = threadIdx.x;
    int lane = t & 31, warp = t >> 5;
    int row = blockIdx.x * 8 + warp;
    if (row >= nrows) return;

    unsigned rt = (unsigned)d_route[lane];
    int ps1 = rt & 31, ps2 = (rt >> 5) & 31;
    unsigned psel = (rt >> 10) & 1u, pswp = (rt >> 11) & 1u;
    unsigned rn = rt >> 16;
    int ns1 = rn & 31, ns2 = (rn >> 5) & 31;
    unsigned nsel = (rn >> 10) & 1u, nswp = (rn >> 11) & 1u;

    const float4* __restrict__ r = x + (long long)row * 64;
    float4*       __restrict__ o = out + (long long)row * 64;

    float4 v0 = r[lane];        // fully coalesced, row read exactly once
    float4 v1 = r[lane + 32];

    float4 plo, phi, nlo, nhi;
    route_gather(v0, v1, ps1, ps2, psel, pswp, plo, phi);
    route_gather(v0, v1, ns1, ns2, nsel, nswp, nlo, nhi);

    float4 olo, ohi;
    olo.x = plo.x - nlo.x;  olo.y = plo.y - nlo.y;
    olo.z = plo.z - nlo.z;  olo.w = plo.w - nlo.w;
    ohi.x = phi.x - nhi.x;  ohi.y = phi.y - nhi.y;
    ohi.z = phi.z - nhi.z;  ohi.w = phi.w - nhi.w;

    o[lane]      = olo;         // fully coalesced stores
    o[lane + 32] = ohi;
}

extern "C" void kernel_launch(void* const* d_in, const int* in_sizes, int n_in,
                              void* d_out, int out_size)
{
    const float4* x    = (const float4*)d_in[0];
    const float*  Ppos = (const float*)d_in[1];
    const float*  Pneg = (const float*)d_in[2];
    float4*       out  = (float4*)d_out;

    int nrows = out_size / 256;                 // 131072
    int blocks = (nrows + 7) / 8;               // 8 warps per block, 1 row per warp

    route_setup<<<1, 32>>>(Ppos, Pneg);
    permute_ws_benes<<<blocks, 256>>>(x, out, nrows);
}